// round 10
// baseline (speedup 1.0000x reference)
#include <cuda_runtime.h>
#include <cuda_bf16.h>
#include <cstdint>

// ============================================================================
// RelativeAttention (sm_103, TF32 HMMA, K-split pipeline, 2 CTAs/SM)
//
// out[bn,i=(h,w),j=(x,y)] = dot(q_i,k_j) + QW[bn,i, y-w+31] + QH[bn,i, x-h+31]
//
// K1 (convert_b): k -> tf32, 16KB units of 128 cols x 32 K, XOR-swizzled
// K2 (attn_hmma): 288 thr = 8 workers + 1 producer, __launch_bounds__(288,2)
//   - q staged linear (A region); ew/eh staged rotated pitch-64 (B region)
//   - exact fp32 qw/qh windows; A image rewritten in place as swizzled tf32
//   - 16 K-split chunks, double-buffered via producer cp.async.bulk
//   - epilogue on odd chunks: smem qw/qh adds, STG.64
// ============================================================================

#define BNB 64
#define LQ  1024
#define DD  64
#define UNIT_BYTES 16384          // 128 cols x 32 K x f32

__device__ __align__(1024) unsigned char g_B[(size_t)1024 * UNIT_BYTES];

typedef unsigned long long ull;

// ---------------- helpers ----------------
__device__ __forceinline__ void ffma2(ull& acc, ull a, ull b) {
    asm("fma.rn.f32x2 %0, %1, %2, %0;" : "+l"(acc) : "l"(a), "l"(b));
}
__device__ __forceinline__ void unpack2(ull v, float& lo, float& hi) {
    asm("mov.b64 {%0, %1}, %2;" : "=f"(lo), "=f"(hi) : "l"(v));
}
__device__ __forceinline__ float tf32r(float x) {
    float r; asm("cvt.rna.tf32.f32 %0, %1;" : "=f"(r) : "f"(x)); return r;
}
__device__ __forceinline__ uint32_t smem_u32(const void* p) {
    uint32_t a;
    asm("{ .reg .u64 t; cvta.to.shared.u64 t, %1; cvt.u32.u64 %0, t; }" : "=r"(a) : "l"(p));
    return a;
}
__device__ __forceinline__ uint32_t elect_one() {
    uint32_t p;
    asm volatile("{ .reg .pred p; elect.sync _|p, 0xFFFFFFFF; selp.b32 %0, 1, 0, p; }" : "=r"(p));
    return p;
}

#define MBAR_INIT(a, c) \
    asm volatile("mbarrier.init.shared.b64 [%0], %1;" :: "r"(a), "r"(c) : "memory")
#define MBAR_EXPECT_TX(a, b) \
    asm volatile("mbarrier.arrive.expect_tx.shared.b64 _, [%0], %1;" :: "r"(a), "r"(b) : "memory")
#define MBAR_ARRIVE(a) \
    asm volatile("mbarrier.arrive.shared.b64 _, [%0];" :: "r"(a) : "memory")
#define MBAR_WAIT(a, ph) do {                                                   \
    asm volatile("{\n\t.reg .pred P1;\n\t"                                      \
        "WL%=:\n\t"                                                             \
        "mbarrier.try_wait.parity.acquire.cta.shared::cta.b64 P1, [%0], %1, 0x989680;\n\t" \
        "@P1 bra.uni WD%=;\n\t bra.uni WL%=;\n\tWD%=:\n\t}"                      \
        :: "r"(a), "r"(ph) : "memory");                                          \
} while (0)

__device__ __forceinline__ void bulk_g2s(uint32_t dst, const void* src, uint32_t bytes, uint32_t mbar) {
    uint64_t gsrc = (uint64_t)__cvta_generic_to_global(src);
    asm volatile("cp.async.bulk.shared::cta.global.mbarrier::complete_tx::bytes [%0], [%1], %2, [%3];"
                 :: "r"(dst), "l"(gsrc), "r"(bytes), "r"(mbar) : "memory");
}

__device__ __forceinline__ void ldsm4(uint32_t& r0, uint32_t& r1, uint32_t& r2, uint32_t& r3,
                                      uint32_t addr) {
    asm volatile("ldmatrix.sync.aligned.m8n8.x4.shared.b16 {%0,%1,%2,%3}, [%4];"
                 : "=r"(r0), "=r"(r1), "=r"(r2), "=r"(r3) : "r"(addr));
}
__device__ __forceinline__ void mma_tf32(float* c, const uint32_t* a, const uint32_t* b) {
    asm volatile("mma.sync.aligned.m16n8k8.row.col.f32.tf32.tf32.f32 "
                 "{%0,%1,%2,%3}, {%4,%5,%6,%7}, {%8,%9}, {%0,%1,%2,%3};"
                 : "+f"(c[0]), "+f"(c[1]), "+f"(c[2]), "+f"(c[3])
                 : "r"(a[0]), "r"(a[1]), "r"(a[2]), "r"(a[3]), "r"(b[0]), "r"(b[1]));
}

// A image: 128 rows x 256B (16 chunks); B unit: 128 rows x 128B (8 chunks)
__device__ __forceinline__ uint32_t img_off_a(int row, int chunk) {
    return (uint32_t)row * 256u + (uint32_t)((chunk ^ (row & 7)) * 16);
}
__device__ __forceinline__ uint32_t img_off_b(int row, int chunk) {
    return (uint32_t)row * 128u + (uint32_t)((chunk ^ (row & 7)) * 16);
}

// ----------------------------------------------------------------------------
// Kernel 1: convert k -> tf32 K-split swizzled units (2 x 16KB per 128-col tile)
// ----------------------------------------------------------------------------
__global__ __launch_bounds__(256) void convert_b_kernel(const float* __restrict__ k)
{
    int unit = blockIdx.x;                       // (bn, ct) pair
    const float* base = k + (size_t)unit * 128 * DD;
    unsigned char* dst = g_B + (size_t)unit * 2 * UNIT_BYTES;
    int tid = threadIdx.x;

    #pragma unroll
    for (int c = 0; c < 4; c++) {
        int chunk = tid + c * 256;          // 0..1023
        int row = chunk >> 3;
        int d0  = (chunk & 7) * 8;          // float index, multiple of 8
        float4 v0 = *(const float4*)&base[row * DD + d0];
        float4 v1 = *(const float4*)&base[row * DD + d0 + 4];
        float4 o0 = make_float4(tf32r(v0.x), tf32r(v0.y), tf32r(v0.z), tf32r(v0.w));
        float4 o1 = make_float4(tf32r(v1.x), tf32r(v1.y), tf32r(v1.z), tf32r(v1.w));
        int c4 = d0 >> 2;                   // 4-float chunk 0..15 (even)
        int kh = c4 >> 3;
        unsigned char* du = dst + kh * UNIT_BYTES;
        *(float4*)(du + img_off_b(row, c4 & 7))       = o0;
        *(float4*)(du + img_off_b(row, (c4 + 1) & 7)) = o1;
    }
}

// ----------------------------------------------------------------------------
// Kernel 2: fused tables + A-convert + TF32 HMMA GEMM + epilogue
// ----------------------------------------------------------------------------
// byte offsets
#define AS_OFF   0                     // A image 32KB (pre-GEMM: q fp32 linear)
#define BS_OFF   32768                 // two 16KB B buffers (pre-GEMM: ew | eh)
#define QW_OFF   65536                 // 128 x pitch40 f32 = 20480
#define QH_OFF   86016                 // 128 x pitch33 f32 = 16896
#define CTRL_OFF 102912
#define SMEM_SZ  102976
// float-index offsets: ew in buffer0, eh in buffer1 (rotated pitch 64)
#define EWF  (BS_OFF / 4)
#define EHF  ((BS_OFF + UNIT_BYTES) / 4)

__global__ __launch_bounds__(288, 2) void attn_hmma_kernel(
    const float* __restrict__ q, const float* __restrict__ ew,
    const float* __restrict__ eh, float* __restrict__ out)
{
    extern __shared__ unsigned char smem[];
    float* smem_f = (float*)smem;
    const uint32_t sb = smem_u32(smem);

    const int bn = blockIdx.x >> 3;
    const int rt = blockIdx.x & 7;
    const int row0 = rt * 128;
    const int n_head = bn & 7;
    const int tid = threadIdx.x, lane = tid & 31, warp = tid >> 5;
    const int warp_r = warp >> 2;     // workers: 0..1 -> 64-row half
    const int warp_c = warp & 3;      // workers: 0..3 -> 32-col strip

    const uint32_t mb0 = sb + CTRL_OFF,      mb1 = mb0 + 8;   // B-full (count 1)
    const uint32_t mc0 = mb0 + 16,           mc1 = mb0 + 24;  // B-consumed (count 8)
    if (tid == 0) {
        MBAR_INIT(mb0, 1); MBAR_INIT(mb1, 1);
        MBAR_INIT(mc0, 8); MBAR_INIT(mc1, 8);
    }

    // ---- phase A: stage q (linear, A region) + ew/eh (rotated pitch 64) ----
    if (tid < 256) {
        const float* ewb = ew + (size_t)n_head * 63 * DD;
        const float* ehb = eh + (size_t)n_head * 63 * DD;
        for (int c = tid; c < 1008; c += 256) {          // 63 rows x 16 float4
            int row = c >> 4, d0 = (c & 15) * 4;
            float4 vw = *(const float4*)&ewb[row * DD + d0];
            float4 vh = *(const float4*)&ehb[row * DD + d0];
            int p0 = (d0 + 2 * row) & 63;                // even -> 8B aligned
            int p1 = (d0 + 2 + 2 * row) & 63;
            *(float2*)&smem_f[EWF + row * 64 + p0] = make_float2(vw.x, vw.y);
            *(float2*)&smem_f[EWF + row * 64 + p1] = make_float2(vw.z, vw.w);
            *(float2*)&smem_f[EHF + row * 64 + p0] = make_float2(vh.x, vh.y);
            *(float2*)&smem_f[EHF + row * 64 + p1] = make_float2(vh.z, vh.w);
        }
        const float* qb = q + ((size_t)bn * LQ + row0) * DD;
        #pragma unroll
        for (int it = 0; it < 8; it++) {                 // 128 rows x 16 float4
            int c = tid + it * 256;
            int row = c >> 4, d0 = (c & 15) * 4;
            *(float4*)&smem_f[row * 64 + d0] = *(const float4*)&qb[(size_t)row * DD + d0];
        }
    }
    __syncthreads();   // S1

    // ---- phase B: exact fp32 qw/qh windows + qreg read ----
    // e row m stores element e at position (e + 2m) & 63 -> q side is broadcast.
    float* qw_s = smem_f + QW_OFF / 4;   // [row][y] pitch 40
    float* qh_s = smem_f + QH_OFF / 4;   // [row][x] pitch 33
    if (warp < 8) {
        #pragma unroll 1
        for (int pass = 0; pass < 32; pass++) {
            int task = warp * 32 + pass;
            bool isW = task < 128;
            int r = isW ? task : task - 128;
            int shift = isW ? (31 - (r & 31)) : (31 - (rt * 4 + (r >> 5)));
            int m = shift + lane;                         // 0..62
            const float* erow = smem_f + (isW ? EWF : EHF) + m * 64;
            const float* qrow = smem_f + (size_t)r * 64;
            int k0 = (2 * m) & 63;
            ull acc = 0;
            #pragma unroll 8
            for (int kk = 0; kk < 32; kk++) {
                ull qp = *(const ull*)(qrow + 2 * kk);    // broadcast
                int idx = (k0 + 2 * kk) & 63;             // holds elems 2kk,2kk+1
                ull ep = *(const ull*)(erow + idx);
                ffma2(acc, qp, ep);
            }
            float vlo, vhi; unpack2(acc, vlo, vhi);
            float v = vlo + vhi;
            if (isW) qw_s[r * 40 + lane] = v;
            else     qh_s[r * 33 + lane] = v;
        }
    }
    // read q chunks this thread will rewrite swizzled
    float qreg[4][8];
    if (tid < 256) {
        #pragma unroll
        for (int c = 0; c < 4; c++) {
            int chunk = tid + c * 256;
            int row = chunk >> 3, d0 = (chunk & 7) * 8;
            float4 v0 = *(const float4*)&smem_f[row * 64 + d0];
            float4 v1 = *(const float4*)&smem_f[row * 64 + d0 + 4];
            qreg[c][0] = v0.x; qreg[c][1] = v0.y; qreg[c][2] = v0.z; qreg[c][3] = v0.w;
            qreg[c][4] = v1.x; qreg[c][5] = v1.y; qreg[c][6] = v1.z; qreg[c][7] = v1.w;
        }
    }
    __syncthreads();   // S2: all q/e reads done; tables written; B region free

    // producer prologue: first two B chunks (overlaps phase C below)
    if (warp == 8 && elect_one()) {
        asm volatile("fence.proxy.async.shared::cta;" ::: "memory");
        MBAR_EXPECT_TX(mb0, UNIT_BYTES);
        bulk_g2s(sb + BS_OFF, g_B + (size_t)bn * 16 * UNIT_BYTES, UNIT_BYTES, mb0);
        MBAR_EXPECT_TX(mb1, UNIT_BYTES);
        bulk_g2s(sb + BS_OFF + UNIT_BYTES, g_B + ((size_t)bn * 16 + 1) * UNIT_BYTES,
                 UNIT_BYTES, mb1);
    }

    // ---- phase C: write swizzled tf32 A image in place ----
    if (tid < 256) {
        #pragma unroll
        for (int c = 0; c < 4; c++) {
            int chunk = tid + c * 256;
            int row = chunk >> 3, d0 = (chunk & 7) * 8;
            float4 o0 = make_float4(tf32r(qreg[c][0]), tf32r(qreg[c][1]),
                                    tf32r(qreg[c][2]), tf32r(qreg[c][3]));
            float4 o1 = make_float4(tf32r(qreg[c][4]), tf32r(qreg[c][5]),
                                    tf32r(qreg[c][6]), tf32r(qreg[c][7]));
            *(float4*)(smem + AS_OFF + img_off_a(row, (d0 >> 2)))     = o0;
            *(float4*)(smem + AS_OFF + img_off_a(row, (d0 >> 2) + 1)) = o1;
        }
    }
    __syncthreads();   // S3: A image ready

    // lane decomposition for ldmatrix addressing (f32 8x4 blocks as b16 m8n8)
    const int r8 = lane & 7;
    const int ma = (lane >> 3) & 1, ka = lane >> 4;       // A: row-half, chunk-half
    const int gb = lane >> 4,       cb = (lane >> 3) & 1; // B: n-group, chunk-half
    const uint32_t a_base = sb + AS_OFF + (uint32_t)(warp_r * 64 + ma * 8 + r8) * 256;

    // epilogue lane mapping
    const int l4 = lane >> 2, l2 = (lane & 3) * 2;
    float* outb = out + ((size_t)bn << 20);

    if (warp < 8) {
        float acc[4][4][4];
        for (int u = 0; u < 16; u++) {                    // u = ct*2 + kh
            const int buf = u & 1;
            const int kh = u & 1;
            MBAR_WAIT(buf ? mb1 : mb0, (u >> 1) & 1);

            const uint32_t b_base = sb + BS_OFF + (uint32_t)buf * UNIT_BYTES
                                  + (uint32_t)(warp_c * 32 + gb * 8 + r8) * 128;

            if (kh == 0) {
                #pragma unroll
                for (int mt = 0; mt < 4; mt++)
                    #pragma unroll
                    for (int nn = 0; nn < 4; nn++)
                        #pragma unroll
                        for (int e = 0; e < 4; e++) acc[mt][nn][e] = 0.f;
            }

            #pragma unroll
            for (int s = 0; s < 4; s++) {
                uint32_t af[4][4];
                const uint32_t ca = (uint32_t)(kh * 128 + ((2 * s + ka) ^ r8) * 16);
                #pragma unroll
                for (int mt = 0; mt < 4; mt++)
                    ldsm4(af[mt][0], af[mt][1], af[mt][2], af[mt][3],
                          a_base + (uint32_t)(mt * 16 * 256) + ca);
                uint32_t bf[2][4];
                const uint32_t cbb = (uint32_t)(((2 * s + cb) ^ r8) * 16);
                #pragma unroll
                for (int np = 0; np < 2; np++)
                    ldsm4(bf[np][0], bf[np][1], bf[np][2], bf[np][3],
                          b_base + (uint32_t)(np * 16 * 128) + cbb);
                #pragma unroll
                for (int mt = 0; mt < 4; mt++)
                    #pragma unroll
                    for (int nn = 0; nn < 4; nn++)
                        mma_tf32(acc[mt][nn], af[mt], &bf[nn >> 1][(nn & 1) * 2]);
            }

            // release this B chunk
            if (elect_one()) MBAR_ARRIVE(buf ? mc1 : mc0);

            // epilogue after the second K-half of each col-tile
            if (kh == 1) {
                const int ct = u >> 1;
                const int xq = ct * 4 + warp_c;           // warp-uniform x index
                #pragma unroll
                for (int mt = 0; mt < 4; mt++) {
                    #pragma unroll
                    for (int half = 0; half < 2; half++) {
                        const int r = warp_r * 64 + mt * 16 + half * 8 + l4;
                        const float hv = qh_s[r * 33 + xq];
                        float* op = outb + (size_t)(row0 + r) * 1024
                                  + ct * 128 + warp_c * 32 + l2;
                        #pragma unroll
                        for (int nn = 0; nn < 4; nn++) {
                            float2 wv = *(const float2*)&qw_s[r * 40 + nn * 8 + l2];
                            float2 o;
                            o.x = acc[mt][nn][half * 2 + 0] + wv.x + hv;
                            o.y = acc[mt][nn][half * 2 + 1] + wv.y + hv;
                            *(float2*)(op + nn * 8) = o;
                        }
                    }
                }
            }
        }
    } else if (warp == 8) {
        // ---- producer: remaining 14 B chunks ----
        if (elect_one()) {
            for (int t = 2; t < 16; t++) {
                const int b = t & 1;
                MBAR_WAIT(b ? mc1 : mc0, ((t - 2) >> 1) & 1);
                MBAR_EXPECT_TX(b ? mb1 : mb0, UNIT_BYTES);
                bulk_g2s(sb + BS_OFF + (uint32_t)b * UNIT_BYTES,
                         g_B + ((size_t)bn * 16 + t) * UNIT_BYTES, UNIT_BYTES,
                         b ? mb1 : mb0);
            }
        }
    }
}

// ----------------------------------------------------------------------------
extern "C" void kernel_launch(void* const* d_in, const int* in_sizes, int n_in,
                              void* d_out, int out_size)
{
    const float* q  = (const float*)d_in[0];
    const float* k  = (const float*)d_in[1];
    const float* ew = (const float*)d_in[2];
    const float* eh = (const float*)d_in[3];
    float* out = (float*)d_out;

    cudaFuncSetAttribute(attn_hmma_kernel, cudaFuncAttributeMaxDynamicSharedMemorySize, SMEM_SZ);

    convert_b_kernel<<<512, 256>>>(k);
    attn_hmma_kernel<<<512, 288, SMEM_SZ>>>(q, ew, eh, out);
}